// round 8
// baseline (speedup 1.0000x reference)
#include <cuda_runtime.h>
#include <math.h>
#include <stdint.h>

// Problem constants
#define BB   32
#define TT   64
#define DD   512
#define HH   512
#define VV   32000
#define G4   2048
#define MROW 2048    // T*B

#define NBLK 128

// ---------------- scratch (__device__ globals) -------------------------------
__device__ float g_xz_enc[MROW * G4];
__device__ float g_xz_dec[MROW * G4];
__device__ float g_X[MROW * DD];
// state: c [32*512] | hp0 packed [16*512*2] | hp1 packed [16*512*2] | bars[16]
__device__ float g_state[3 * BB * HH + 16];
__device__ float g_hs[BB * TT * HH];
__device__ float g_WtP[(size_t)VV * DD];
__device__ float g_WtE[(size_t)G4 * DD];
__device__ float g_WtD[(size_t)G4 * DD];

__device__ __forceinline__ float sigf(float x) { return 1.0f / (1.0f + expf(-x)); }

__device__ __forceinline__ float f2tf(float x) {
    uint32_t r;
    asm("cvt.rna.tf32.f32 %0, %1;" : "=r"(r) : "f"(x));
    return __uint_as_float(r);
}

__device__ __forceinline__ uint32_t s2u(const void* p) {
    uint32_t a;
    asm("{ .reg .u64 t; cvta.to.shared.u64 t, %1; cvt.u32.u64 %0, t; }" : "=r"(a) : "l"(p));
    return a;
}

#define CP_ASYNC16(sdst, gsrc) \
    asm volatile("cp.async.cg.shared.global [%0], [%1], 16;" :: "r"(sdst), "l"(gsrc))
#define CP_COMMIT() asm volatile("cp.async.commit_group;" ::: "memory")
#define CP_WAIT1()  asm volatile("cp.async.wait_group 1;" ::: "memory")
#define CP_WAIT0()  asm volatile("cp.async.wait_group 0;" ::: "memory")

#define LDSM_X4(r0, r1, r2, r3, addr) \
    asm volatile("ldmatrix.sync.aligned.m8n8.x4.shared.b16 {%0,%1,%2,%3}, [%4];" \
        : "=r"(r0), "=r"(r1), "=r"(r2), "=r"(r3) : "r"(addr))

#define MMA_TF32(c, a, b0, b1) \
    asm volatile("mma.sync.aligned.m16n8k8.row.col.f32.tf32.tf32.f32 " \
        "{%0,%1,%2,%3}, {%4,%5,%6,%7}, {%8,%9}, {%0,%1,%2,%3};" \
        : "+f"((c)[0]), "+f"((c)[1]), "+f"((c)[2]), "+f"((c)[3]) \
        : "r"((a)[0]), "r"((a)[1]), "r"((a)[2]), "r"((a)[3]), "r"(b0), "r"(b1))

// packed fp32x2 ops
__device__ __forceinline__ void ffma2(unsigned long long& d, unsigned long long a,
                                      unsigned long long b) {
    asm("fma.rn.f32x2 %0, %1, %2, %0;" : "+l"(d) : "l"(a), "l"(b));
}
__device__ __forceinline__ unsigned long long fadd2(unsigned long long a,
                                                    unsigned long long b) {
    unsigned long long d;
    asm("add.rn.f32x2 %0, %1, %2;" : "=l"(d) : "l"(a), "l"(b));
    return d;
}
__device__ __forceinline__ unsigned long long packf2(float x, float y) {
    unsigned long long r;
    asm("mov.b64 %0, {%1, %2};" : "=l"(r) : "r"(__float_as_uint(x)), "r"(__float_as_uint(y)));
    return r;
}
__device__ __forceinline__ void unpackf2(unsigned long long v, float& x, float& y) {
    uint32_t a, b;
    asm("mov.b64 {%0, %1}, %2;" : "=r"(a), "=r"(b) : "l"(v));
    x = __uint_as_float(a);
    y = __uint_as_float(b);
}

// ---------------- small kernels ---------------------------------------------
// dst[c][r] = tf32(src[r][c]); src is [R, C] row-major
__global__ void transpose_kernel(const float* __restrict__ src, float* __restrict__ dst,
                                 int R, int C) {
    __shared__ float tile[32][33];
    int c0 = blockIdx.x * 32, r0 = blockIdx.y * 32;
    int tx = threadIdx.x, ty = threadIdx.y;  // (32, 8)
    #pragma unroll
    for (int i = 0; i < 32; i += 8)
        tile[ty + i][tx] = src[(size_t)(r0 + ty + i) * C + c0 + tx];
    __syncthreads();
    #pragma unroll
    for (int i = 0; i < 32; i += 8)
        dst[(size_t)(c0 + ty + i) * R + r0 + tx] = f2tf(tile[tx][ty + i]);
}

// embed + (optionally) zero the LSTM grid-barrier counters
__global__ void embed_kernel(const int* __restrict__ ids, const float* __restrict__ E,
                             float* __restrict__ X, unsigned* __restrict__ bars) {
    if (bars && blockIdx.x == 0 && threadIdx.x < 16) bars[threadIdx.x] = 0u;
    int r = blockIdx.x;
    int t = r >> 5;
    int b = r & 31;
    int tok = ids[b * TT + t];
    const float4* src = (const float4*)(E + (size_t)tok * DD);
    float4 v = src[threadIdx.x];
    v.x = f2tf(v.x); v.y = f2tf(v.y); v.z = f2tf(v.z); v.w = f2tf(v.w);
    ((float4*)(X + (size_t)r * DD))[threadIdx.x] = v;
}

// ---------------- tf32 mma.sync GEMM (BN=128, validated R6) ------------------
__device__ __forceinline__ void ld_tile(const float* __restrict__ src, size_t row0,
                                        int kc, uint32_t sbase, int tid) {
    #pragma unroll
    for (int i = 0; i < 4; i++) {
        int s = tid + i * 256;
        int r = s >> 3, cs = s & 7;
        const float* g = src + (row0 + r) * DD + kc * 32 + cs * 4;
        uint32_t off = (uint32_t)(r * 128 + cs * 16) ^ ((r & 7) << 4);
        CP_ASYNC16(sbase + off, g);
    }
}

#define TILE_B 16384
#define GEMM_SMEM (1024 + 4 * TILE_B)

__global__ __launch_bounds__(256)
void tf32_gemm_kernel(const float* __restrict__ A, const float* __restrict__ Bt,
                      const float* __restrict__ bias, float* __restrict__ C, int ldc) {
    extern __shared__ char smem_raw[];
    uint32_t raw_u = s2u(smem_raw);
    uint32_t base_u = (raw_u + 1023) & ~1023u;
    uint32_t sa_u[2] = { base_u,          base_u + 2 * TILE_B };
    uint32_t sb_u[2] = { base_u + TILE_B, base_u + 3 * TILE_B };

    int tid = threadIdx.x;
    int lane = tid & 31, wid = tid >> 5;
    int wm = wid & 3, wn = wid >> 2;
    size_t m0 = (size_t)blockIdx.y * 128;
    size_t n0 = (size_t)blockIdx.x * 128;

    int q = lane >> 3;
    int ar = wm * 32 + (q & 1) * 8 + (lane & 7);
    uint32_t apre[2], amask = (uint32_t)((ar & 7) << 4);
    apre[0] = (uint32_t)(ar * 128 + (q >> 1) * 16);
    apre[1] = apre[0] + 16 * 128;
    int br = wn * 64 + (q >> 1) * 8 + (lane & 7);
    uint32_t bpre[4], bmask = (uint32_t)((br & 7) << 4);
    bpre[0] = (uint32_t)(br * 128 + (q & 1) * 16);
    bpre[1] = bpre[0] + 16 * 128;
    bpre[2] = bpre[0] + 32 * 128;
    bpre[3] = bpre[0] + 48 * 128;

    float acc[2][8][4];
    #pragma unroll
    for (int i = 0; i < 2; i++)
        #pragma unroll
        for (int j = 0; j < 8; j++)
            #pragma unroll
            for (int k = 0; k < 4; k++) acc[i][j][k] = 0.0f;

    ld_tile(A,  m0, 0, sa_u[0], tid);
    ld_tile(Bt, n0, 0, sb_u[0], tid);
    CP_COMMIT();

    int buf = 0;
    #pragma unroll 1
    for (int it = 0; it < DD / 32; it++) {
        if (it + 1 < DD / 32) {
            ld_tile(A,  m0, it + 1, sa_u[buf ^ 1], tid);
            ld_tile(Bt, n0, it + 1, sb_u[buf ^ 1], tid);
            CP_COMMIT();
            CP_WAIT1();
        } else {
            CP_WAIT0();
        }
        __syncthreads();

        uint32_t As = sa_u[buf], Bs = sb_u[buf];
        #pragma unroll
        for (int ks = 0; ks < 4; ks++) {
            uint32_t a[2][4], b[4][4];
            #pragma unroll
            for (int mt = 0; mt < 2; mt++)
                LDSM_X4(a[mt][0], a[mt][1], a[mt][2], a[mt][3],
                        As + (((apre[mt] + ks * 32) ^ amask)));
            #pragma unroll
            for (int np = 0; np < 4; np++)
                LDSM_X4(b[np][0], b[np][1], b[np][2], b[np][3],
                        Bs + (((bpre[np] + ks * 32) ^ bmask)));
            #pragma unroll
            for (int mt = 0; mt < 2; mt++)
                #pragma unroll
                for (int nt = 0; nt < 8; nt++)
                    MMA_TF32(acc[mt][nt], a[mt], b[nt >> 1][(nt & 1) * 2],
                             b[nt >> 1][(nt & 1) * 2 + 1]);
        }
        __syncthreads();
        buf ^= 1;
    }

    int g = lane >> 2, tg = lane & 3;
    #pragma unroll
    for (int mt = 0; mt < 2; mt++) {
        size_t row = m0 + wm * 32 + mt * 16 + g;
        #pragma unroll
        for (int nt = 0; nt < 8; nt++) {
            size_t col = n0 + wn * 64 + nt * 8 + 2 * tg;
            float b0 = 0.f, b1 = 0.f;
            if (bias) { b0 = bias[col]; b1 = bias[col + 1]; }
            float2 v0 = make_float2(acc[mt][nt][0] + b0, acc[mt][nt][1] + b1);
            float2 v1 = make_float2(acc[mt][nt][2] + b0, acc[mt][nt][3] + b1);
            *(float2*)(C + row * (size_t)ldc + col)       = v0;
            *(float2*)(C + (row + 8) * (size_t)ldc + col) = v1;
        }
    }
}

// ---------------- persistent LSTM v3 -----------------------------------------
// 128 blocks = 32 col-tiles (16 units) x 4 batch-quarters (8 batches).
// Thread layout: colq = tid>>4 (16 quads of 4 consecutive cols), kg = tid&15
// (16 groups of 32 k). 4 cols share each h read -> 16 FFMA2 per 4 LDS.64
// (4x less SMEM traffic than v2). Weights: 128 regs, float4-loadable.
// Reduction: width-16 shuffles. Barrier: red.release + ld.acquire.
__global__ __launch_bounds__(256)
void lstm_persistent3(const float* __restrict__ xz, const float* __restrict__ Wh,
                      const int* __restrict__ len, float* __restrict__ c_glob,
                      float* __restrict__ hp0f, float* __restrict__ hp1f,
                      float* __restrict__ hs, unsigned* __restrict__ bar, int dec) {
    __shared__ unsigned long long hp_s[4 * 512];   // 8 batches packed: [pair][k]
    __shared__ float z_s[64][12];
    int tid = threadIdx.x;
    int colq = tid >> 4, kg = tid & 15;
    int ux = blockIdx.x & 31, bq = blockIdx.x >> 5;
    int u0 = ux * 16, b0 = bq * 8;
    // this thread's 4 consecutive global columns: gate*512 + u0 + (colq&3)*4 + c
    int jgbase = ((colq >> 2) << 9) + u0 + (colq & 3) * 4;

    // weights: w[c][i] = Wh[(kg*32+i)][jgbase+c], coalesced float4 loads
    float wreg[4][32];
    #pragma unroll
    for (int i = 0; i < 32; i++) {
        float4 wv = *(const float4*)(Wh + (size_t)(kg * 32 + i) * G4 + jgbase);
        wreg[0][i] = wv.x; wreg[1][i] = wv.y; wreg[2][i] = wv.z; wreg[3][i] = wv.w;
    }

    // gate-thread identity (tid < 128)
    int u = tid & 15, bb = tid >> 4;
    int b = b0 + bb, uu = u0 + u;
    int myl = 0;
    float cval = 0.0f;
    if (tid < 128) {
        myl = len[b];
        if (dec) cval = c_glob[(size_t)b * HH + uu];
    }

    const unsigned long long* hpg[2] = {
        (const unsigned long long*)hp0f + (size_t)bq * 4 * 512,
        (const unsigned long long*)hp1f + (size_t)bq * 4 * 512 };
    float* hpw[2] = { hp0f, hp1f };
    unsigned target = 0;

    #pragma unroll 1
    for (int t = 0; t < TT; t++) {
        bool first = (t == 0) && (dec == 0);   // encoder h0 == 0
        float xzv[4];
        if (tid < 128) {
            const float* xp = xz + (size_t)(t * BB + b) * G4 + uu;
            #pragma unroll
            for (int g = 0; g < 4; g++) xzv[g] = xp[g * HH];
        }
        if (!first) {
            {   // stage packed h (16KB) for this block's 8 batches
                const float4* src = (const float4*)hpg[t & 1];
                float4* dst = (float4*)hp_s;
                #pragma unroll
                for (int i = 0; i < 4; i++) dst[tid + i * 256] = src[tid + i * 256];
            }
            __syncthreads();

            unsigned long long acc2[4][4];
            #pragma unroll
            for (int cc = 0; cc < 4; cc++)
                #pragma unroll
                for (int p = 0; p < 4; p++) acc2[cc][p] = 0ull;

            #pragma unroll
            for (int i = 0; i < 32; i++) {
                int k = kg * 32 + i;
                unsigned long long h0 = hp_s[k];
                unsigned long long h1 = hp_s[512 + k];
                unsigned long long h2 = hp_s[1024 + k];
                unsigned long long h3 = hp_s[1536 + k];
                #pragma unroll
                for (int cc = 0; cc < 4; cc++) {
                    unsigned long long wd = packf2(wreg[cc][i], wreg[cc][i]);
                    ffma2(acc2[cc][0], wd, h0);
                    ffma2(acc2[cc][1], wd, h1);
                    ffma2(acc2[cc][2], wd, h2);
                    ffma2(acc2[cc][3], wd, h3);
                }
            }
            // reduce across the 16 kg lanes
            #pragma unroll
            for (int r = 1; r < 16; r <<= 1)
                #pragma unroll
                for (int cc = 0; cc < 4; cc++)
                    #pragma unroll
                    for (int p = 0; p < 4; p++)
                        acc2[cc][p] = fadd2(acc2[cc][p],
                            __shfl_xor_sync(0xffffffffu, acc2[cc][p], r, 16));
            if (kg == 0) {
                #pragma unroll
                for (int cc = 0; cc < 4; cc++) {
                    int jl = colq * 4 + cc;
                    #pragma unroll
                    for (int p = 0; p < 4; p++) {
                        float x, y;
                        unpackf2(acc2[cc][p], x, y);
                        z_s[jl][2 * p]     = x;
                        z_s[jl][2 * p + 1] = y;
                    }
                }
            }
            __syncthreads();
        }

        if (tid < 128) {
            float zi = xzv[0], zj = xzv[1], zf = xzv[2], zo = xzv[3];
            if (!first) {
                zi += z_s[u][bb];
                zj += z_s[16 + u][bb];
                zf += z_s[32 + u][bb];
                zo += z_s[48 + u][bb];
            }
            float* hn_dst = hpw[(t + 1) & 1] + ((size_t)(b >> 1) * 512 + uu) * 2 + (b & 1);
            if (t < myl) {
                cval = cval * sigf(zf + 1.0f) + sigf(zi) * tanhf(zj);
                float hn = tanhf(cval) * sigf(zo);
                *hn_dst = hn;
                if (dec) hs[((size_t)b * TT + t) * HH + uu] = f2tf(hn);
            } else {
                float hprev = first ? 0.0f
                    : ((const float*)hp_s)[((size_t)(bb >> 1) * 512 + uu) * 2 + (b & 1)];
                *hn_dst = hprev;
                if (dec) hs[((size_t)b * TT + t) * HH + uu] = 0.0f;
            }
        }
        __syncthreads();
        // per-bq grid barrier (32 blocks): release-add + acquire poll
        target += 32;
        if (tid == 0) {
            asm volatile("red.release.gpu.global.add.u32 [%0], %1;"
                         :: "l"(&bar[bq]), "r"(1u) : "memory");
            unsigned v;
            do {
                asm volatile("ld.acquire.gpu.u32 %0, [%1];" : "=r"(v) : "l"(&bar[bq]));
            } while (v < target);
        }
        __syncthreads();
    }
    if (tid < 128) c_glob[(size_t)b * HH + uu] = cval;
}

// ---------------- host launch ------------------------------------------------
extern "C" void kernel_launch(void* const* d_in, const int* in_sizes, int n_in,
                              void* d_out, int out_size) {
    const int*   enc_ids = (const int*)d_in[0];
    const int*   dec_ids = (const int*)d_in[1];
    const int*   len_enc = (const int*)d_in[2];
    const int*   len_dec = (const int*)d_in[3];
    const float* E       = (const float*)d_in[4];
    const float* enc_W   = (const float*)d_in[5];
    const float* enc_b   = (const float*)d_in[6];
    const float* dec_W   = (const float*)d_in[7];
    const float* dec_b   = (const float*)d_in[8];
    const float* proj_W  = (const float*)d_in[9];
    float* out = (float*)d_out;

    float *xz_e, *xz_d, *X, *state, *hs, *WtP, *WtE, *WtD;
    cudaGetSymbolAddress((void**)&xz_e,  g_xz_enc);
    cudaGetSymbolAddress((void**)&xz_d,  g_xz_dec);
    cudaGetSymbolAddress((void**)&X,     g_X);
    cudaGetSymbolAddress((void**)&state, g_state);
    cudaGetSymbolAddress((void**)&hs,    g_hs);
    cudaGetSymbolAddress((void**)&WtP,   g_WtP);
    cudaGetSymbolAddress((void**)&WtE,   g_WtE);
    cudaGetSymbolAddress((void**)&WtD,   g_WtD);
    float* c   = state;
    float* hp0 = state + BB * HH;
    float* hp1 = state + 2 * BB * HH;
    unsigned* bars = (unsigned*)(state + 3 * BB * HH);

    cudaFuncSetAttribute(tf32_gemm_kernel,
                         cudaFuncAttributeMaxDynamicSharedMemorySize, GEMM_SMEM);

    // [0] enc transpose, [1] enc embed (+zero bars), [2] enc input GEMM
    transpose_kernel<<<dim3(G4 / 32, DD / 32), dim3(32, 8)>>>(enc_W, WtE, DD, G4);
    embed_kernel<<<MROW, 128>>>(enc_ids, E, X, bars);
    tf32_gemm_kernel<<<dim3(G4 / 128, MROW / 128), 256, GEMM_SMEM>>>(X, WtE, enc_b, xz_e, G4);
    // [3] encoder LSTM  <- profiled (ncu launch index 3)
    lstm_persistent3<<<NBLK, 256>>>(xz_e, enc_W + (size_t)DD * G4, len_enc,
                                    c, hp0, hp1, nullptr, bars, 0);

    // [4..6] decoder preprocessing
    transpose_kernel<<<dim3(G4 / 32, DD / 32), dim3(32, 8)>>>(dec_W, WtD, DD, G4);
    embed_kernel<<<MROW, 128>>>(dec_ids, E, X, nullptr);
    tf32_gemm_kernel<<<dim3(G4 / 128, MROW / 128), 256, GEMM_SMEM>>>(X, WtD, dec_b, xz_d, G4);
    // [7] decoder LSTM
    lstm_persistent3<<<NBLK, 256>>>(xz_d, dec_W + (size_t)DD * G4, len_dec,
                                    c, hp0, hp1, hs, bars + 4, 1);

    // [8] proj transpose, [9] vocab projection
    transpose_kernel<<<dim3(VV / 32, DD / 32), dim3(32, 8)>>>(proj_W, WtP, DD, VV);
    tf32_gemm_kernel<<<dim3(VV / 128, MROW / 128), 256, GEMM_SMEM>>>(hs, WtP, nullptr, out, VV);
}

// round 9
// speedup vs baseline: 1.0922x; 1.0922x over previous
#include <cuda_runtime.h>
#include <math.h>
#include <stdint.h>

// Problem constants
#define BB   32
#define TT   64
#define DD   512
#define HH   512
#define VV   32000
#define G4   2048
#define MROW 2048    // T*B

#define NBLK 128

// ---------------- scratch (__device__ globals) -------------------------------
__device__ float g_xz_enc[MROW * G4];
__device__ float g_xz_dec[MROW * G4];
__device__ float g_X[MROW * DD];
// state: c [32*512] | hp0 [16384] | hp1 [16384] | bars[16]
// hp layout: per bq (4096 floats): [k:512][pair:4][half:2]
__device__ float g_state[3 * BB * HH + 16];
__device__ float g_hs[BB * TT * HH];
__device__ float g_WtP[(size_t)VV * DD];
__device__ float g_WtE[(size_t)G4 * DD];
__device__ float g_WtD[(size_t)G4 * DD];

__device__ __forceinline__ float sigf(float x) { return 1.0f / (1.0f + expf(-x)); }

__device__ __forceinline__ float f2tf(float x) {
    uint32_t r;
    asm("cvt.rna.tf32.f32 %0, %1;" : "=r"(r) : "f"(x));
    return __uint_as_float(r);
}

__device__ __forceinline__ uint32_t s2u(const void* p) {
    uint32_t a;
    asm("{ .reg .u64 t; cvta.to.shared.u64 t, %1; cvt.u32.u64 %0, t; }" : "=r"(a) : "l"(p));
    return a;
}

#define CP_ASYNC16(sdst, gsrc) \
    asm volatile("cp.async.cg.shared.global [%0], [%1], 16;" :: "r"(sdst), "l"(gsrc))
#define CP_COMMIT() asm volatile("cp.async.commit_group;" ::: "memory")
#define CP_WAIT1()  asm volatile("cp.async.wait_group 1;" ::: "memory")
#define CP_WAIT0()  asm volatile("cp.async.wait_group 0;" ::: "memory")

#define LDSM_X4(r0, r1, r2, r3, addr) \
    asm volatile("ldmatrix.sync.aligned.m8n8.x4.shared.b16 {%0,%1,%2,%3}, [%4];" \
        : "=r"(r0), "=r"(r1), "=r"(r2), "=r"(r3) : "r"(addr))

#define MMA_TF32(c, a, b0, b1) \
    asm volatile("mma.sync.aligned.m16n8k8.row.col.f32.tf32.tf32.f32 " \
        "{%0,%1,%2,%3}, {%4,%5,%6,%7}, {%8,%9}, {%0,%1,%2,%3};" \
        : "+f"((c)[0]), "+f"((c)[1]), "+f"((c)[2]), "+f"((c)[3]) \
        : "r"((a)[0]), "r"((a)[1]), "r"((a)[2]), "r"((a)[3]), "r"(b0), "r"(b1))

// packed fp32x2 ops
__device__ __forceinline__ void ffma2(unsigned long long& d, unsigned long long a,
                                      unsigned long long b) {
    asm("fma.rn.f32x2 %0, %1, %2, %0;" : "+l"(d) : "l"(a), "l"(b));
}
__device__ __forceinline__ unsigned long long fadd2(unsigned long long a,
                                                    unsigned long long b) {
    unsigned long long d;
    asm("add.rn.f32x2 %0, %1, %2;" : "=l"(d) : "l"(a), "l"(b));
    return d;
}
__device__ __forceinline__ unsigned long long packf2(float x, float y) {
    unsigned long long r;
    asm("mov.b64 %0, {%1, %2};" : "=l"(r) : "r"(__float_as_uint(x)), "r"(__float_as_uint(y)));
    return r;
}
__device__ __forceinline__ void unpackf2(unsigned long long v, float& x, float& y) {
    uint32_t a, b;
    asm("mov.b64 {%0, %1}, %2;" : "=r"(a), "=r"(b) : "l"(v));
    x = __uint_as_float(a);
    y = __uint_as_float(b);
}

// ---------------- small kernels ---------------------------------------------
__global__ void transpose_kernel(const float* __restrict__ src, float* __restrict__ dst,
                                 int R, int C) {
    __shared__ float tile[32][33];
    int c0 = blockIdx.x * 32, r0 = blockIdx.y * 32;
    int tx = threadIdx.x, ty = threadIdx.y;  // (32, 8)
    #pragma unroll
    for (int i = 0; i < 32; i += 8)
        tile[ty + i][tx] = src[(size_t)(r0 + ty + i) * C + c0 + tx];
    __syncthreads();
    #pragma unroll
    for (int i = 0; i < 32; i += 8)
        dst[(size_t)(c0 + ty + i) * R + r0 + tx] = f2tf(tile[tx][ty + i]);
}

__global__ void embed_kernel(const int* __restrict__ ids, const float* __restrict__ E,
                             float* __restrict__ X, unsigned* __restrict__ bars) {
    if (bars && blockIdx.x == 0 && threadIdx.x < 16) bars[threadIdx.x] = 0u;
    int r = blockIdx.x;
    int t = r >> 5;
    int b = r & 31;
    int tok = ids[b * TT + t];
    const float4* src = (const float4*)(E + (size_t)tok * DD);
    float4 v = src[threadIdx.x];
    v.x = f2tf(v.x); v.y = f2tf(v.y); v.z = f2tf(v.z); v.w = f2tf(v.w);
    ((float4*)(X + (size_t)r * DD))[threadIdx.x] = v;
}

// ---------------- tf32 mma.sync GEMM (BN=128, validated R6) ------------------
__device__ __forceinline__ void ld_tile(const float* __restrict__ src, size_t row0,
                                        int kc, uint32_t sbase, int tid) {
    #pragma unroll
    for (int i = 0; i < 4; i++) {
        int s = tid + i * 256;
        int r = s >> 3, cs = s & 7;
        const float* g = src + (row0 + r) * DD + kc * 32 + cs * 4;
        uint32_t off = (uint32_t)(r * 128 + cs * 16) ^ ((r & 7) << 4);
        CP_ASYNC16(sbase + off, g);
    }
}

#define TILE_B 16384
#define GEMM_SMEM (1024 + 4 * TILE_B)

__global__ __launch_bounds__(256)
void tf32_gemm_kernel(const float* __restrict__ A, const float* __restrict__ Bt,
                      const float* __restrict__ bias, float* __restrict__ C, int ldc) {
    extern __shared__ char smem_raw[];
    uint32_t raw_u = s2u(smem_raw);
    uint32_t base_u = (raw_u + 1023) & ~1023u;
    uint32_t sa_u[2] = { base_u,          base_u + 2 * TILE_B };
    uint32_t sb_u[2] = { base_u + TILE_B, base_u + 3 * TILE_B };

    int tid = threadIdx.x;
    int lane = tid & 31, wid = tid >> 5;
    int wm = wid & 3, wn = wid >> 2;
    size_t m0 = (size_t)blockIdx.y * 128;
    size_t n0 = (size_t)blockIdx.x * 128;

    int q = lane >> 3;
    int ar = wm * 32 + (q & 1) * 8 + (lane & 7);
    uint32_t apre[2], amask = (uint32_t)((ar & 7) << 4);
    apre[0] = (uint32_t)(ar * 128 + (q >> 1) * 16);
    apre[1] = apre[0] + 16 * 128;
    int br = wn * 64 + (q >> 1) * 8 + (lane & 7);
    uint32_t bpre[4], bmask = (uint32_t)((br & 7) << 4);
    bpre[0] = (uint32_t)(br * 128 + (q & 1) * 16);
    bpre[1] = bpre[0] + 16 * 128;
    bpre[2] = bpre[0] + 32 * 128;
    bpre[3] = bpre[0] + 48 * 128;

    float acc[2][8][4];
    #pragma unroll
    for (int i = 0; i < 2; i++)
        #pragma unroll
        for (int j = 0; j < 8; j++)
            #pragma unroll
            for (int k = 0; k < 4; k++) acc[i][j][k] = 0.0f;

    ld_tile(A,  m0, 0, sa_u[0], tid);
    ld_tile(Bt, n0, 0, sb_u[0], tid);
    CP_COMMIT();

    int buf = 0;
    #pragma unroll 1
    for (int it = 0; it < DD / 32; it++) {
        if (it + 1 < DD / 32) {
            ld_tile(A,  m0, it + 1, sa_u[buf ^ 1], tid);
            ld_tile(Bt, n0, it + 1, sb_u[buf ^ 1], tid);
            CP_COMMIT();
            CP_WAIT1();
        } else {
            CP_WAIT0();
        }
        __syncthreads();

        uint32_t As = sa_u[buf], Bs = sb_u[buf];
        #pragma unroll
        for (int ks = 0; ks < 4; ks++) {
            uint32_t a[2][4], b[4][4];
            #pragma unroll
            for (int mt = 0; mt < 2; mt++)
                LDSM_X4(a[mt][0], a[mt][1], a[mt][2], a[mt][3],
                        As + (((apre[mt] + ks * 32) ^ amask)));
            #pragma unroll
            for (int np = 0; np < 4; np++)
                LDSM_X4(b[np][0], b[np][1], b[np][2], b[np][3],
                        Bs + (((bpre[np] + ks * 32) ^ bmask)));
            #pragma unroll
            for (int mt = 0; mt < 2; mt++)
                #pragma unroll
                for (int nt = 0; nt < 8; nt++)
                    MMA_TF32(acc[mt][nt], a[mt], b[nt >> 1][(nt & 1) * 2],
                             b[nt >> 1][(nt & 1) * 2 + 1]);
        }
        __syncthreads();
        buf ^= 1;
    }

    int g = lane >> 2, tg = lane & 3;
    #pragma unroll
    for (int mt = 0; mt < 2; mt++) {
        size_t row = m0 + wm * 32 + mt * 16 + g;
        #pragma unroll
        for (int nt = 0; nt < 8; nt++) {
            size_t col = n0 + wn * 64 + nt * 8 + 2 * tg;
            float b0 = 0.f, b1 = 0.f;
            if (bias) { b0 = bias[col]; b1 = bias[col + 1]; }
            float2 v0 = make_float2(acc[mt][nt][0] + b0, acc[mt][nt][1] + b1);
            float2 v1 = make_float2(acc[mt][nt][2] + b0, acc[mt][nt][3] + b1);
            *(float2*)(C + row * (size_t)ldc + col)       = v0;
            *(float2*)(C + (row + 8) * (size_t)ldc + col) = v1;
        }
    }
}

// ---------------- persistent LSTM v4 -----------------------------------------
// 128 blocks = 32 col-tiles x 4 batch-quarters, 512 THREADS.
// Thread (jl, kq): jl = column 0..63, kq = k-octant 0..7 (64 k each).
// h layout [k][pair(4)]: 32 B contiguous per k -> 2 LDS.128 per k feeds 4 FFMA2.
// Reduction: 3 shuffle rounds over 8 kq lanes. v2 structure otherwise.
__global__ __launch_bounds__(512)
void lstm_persistent4(const float* __restrict__ xz, const float* __restrict__ Wh,
                      const int* __restrict__ len, float* __restrict__ c_glob,
                      float* __restrict__ hp0f, float* __restrict__ hp1f,
                      float* __restrict__ hs, unsigned* __restrict__ bar, int dec) {
    __shared__ unsigned long long hp_s[512 * 4];   // [k][pair]
    __shared__ float z_s[64][12];
    int tid = threadIdx.x;
    int w = tid >> 5, l = tid & 31;
    int jl = w * 4 + (l >> 3);          // 0..63
    int kq = l & 7;                     // 0..7
    int ux = blockIdx.x & 31, bq = blockIdx.x >> 5;
    int u0 = ux * 16, b0 = bq * 8;
    int jg = ((jl >> 4) << 9) + u0 + (jl & 15);

    // weights: thread owns k = 8i + kq, column jg
    float wreg[64];
    #pragma unroll
    for (int i = 0; i < 64; i++)
        wreg[i] = Wh[(size_t)(8 * i + kq) * G4 + jg];

    // gate-thread identity (tid < 128)
    int u = tid & 15, bb = (tid >> 4) & 7;
    int b = b0 + bb, uu = u0 + u;
    int myl = 0;
    float cval = 0.0f;
    if (tid < 128) {
        myl = len[b];
        if (dec) cval = c_glob[(size_t)b * HH + uu];
    }

    const float4* hpg[2] = {
        (const float4*)(hp0f + (size_t)bq * 4096),
        (const float4*)(hp1f + (size_t)bq * 4096) };
    float* hpw[2] = { hp0f + (size_t)bq * 4096, hp1f + (size_t)bq * 4096 };
    unsigned target = 0;

    #pragma unroll 1
    for (int t = 0; t < TT; t++) {
        bool first = (t == 0) && (dec == 0);   // encoder h0 == 0
        float xzv[4];
        if (tid < 128) {
            const float* xp = xz + (size_t)(t * BB + b) * G4 + uu;
            #pragma unroll
            for (int g = 0; g < 4; g++) xzv[g] = xp[g * HH];
        }
        if (!first) {
            {   // stage 16 KB of packed h: 1024 float4, 2 per thread
                const float4* src = hpg[t & 1];
                float4* dst = (float4*)hp_s;
                dst[tid]       = src[tid];
                dst[tid + 512] = src[tid + 512];
            }
            __syncthreads();

            unsigned long long acc2[4] = {0ull, 0ull, 0ull, 0ull};
            #pragma unroll
            for (int i = 0; i < 64; i++) {
                int k = 8 * i + kq;
                unsigned long long wd = packf2(wreg[i], wreg[i]);
                const unsigned long long* hk = &hp_s[k * 4];
                ffma2(acc2[0], wd, hk[0]);
                ffma2(acc2[1], wd, hk[1]);
                ffma2(acc2[2], wd, hk[2]);
                ffma2(acc2[3], wd, hk[3]);
            }
            // reduce across 8 kq lanes (3 rounds x 4 ull)
            #pragma unroll
            for (int r = 1; r < 8; r <<= 1)
                #pragma unroll
                for (int p = 0; p < 4; p++)
                    acc2[p] = fadd2(acc2[p],
                        __shfl_xor_sync(0xffffffffu, acc2[p], r, 8));
            if (kq == 0) {
                #pragma unroll
                for (int p = 0; p < 4; p++) {
                    float x, y;
                    unpackf2(acc2[p], x, y);
                    z_s[jl][2 * p]     = x;
                    z_s[jl][2 * p + 1] = y;
                }
            }
            __syncthreads();
        }

        if (tid < 128) {
            float zi = xzv[0], zj = xzv[1], zf = xzv[2], zo = xzv[3];
            if (!first) {
                zi += z_s[u][bb];
                zj += z_s[16 + u][bb];
                zf += z_s[32 + u][bb];
                zo += z_s[48 + u][bb];
            }
            // write h_next in [k][pair][half] layout
            float* hn_dst = hpw[(t + 1) & 1] + uu * 8 + (bb >> 1) * 2 + (bb & 1);
            if (t < myl) {
                cval = cval * sigf(zf + 1.0f) + sigf(zi) * tanhf(zj);
                float hn = tanhf(cval) * sigf(zo);
                *hn_dst = hn;
                if (dec) hs[((size_t)b * TT + t) * HH + uu] = f2tf(hn);
            } else {
                float hprev = first ? 0.0f
                    : ((const float*)hp_s)[uu * 8 + (bb >> 1) * 2 + (bb & 1)];
                *hn_dst = hprev;
                if (dec) hs[((size_t)b * TT + t) * HH + uu] = 0.0f;
            }
        }
        __syncthreads();
        // per-bq grid barrier (32 blocks)
        target += 32;
        if (tid == 0) {
            asm volatile("red.release.gpu.global.add.u32 [%0], %1;"
                         :: "l"(&bar[bq]), "r"(1u) : "memory");
            unsigned v;
            do {
                asm volatile("ld.acquire.gpu.u32 %0, [%1];" : "=r"(v) : "l"(&bar[bq]));
            } while (v < target);
        }
        __syncthreads();
    }
    if (tid < 128) c_glob[(size_t)b * HH + uu] = cval;
}

// ---------------- host launch ------------------------------------------------
extern "C" void kernel_launch(void* const* d_in, const int* in_sizes, int n_in,
                              void* d_out, int out_size) {
    const int*   enc_ids = (const int*)d_in[0];
    const int*   dec_ids = (const int*)d_in[1];
    const int*   len_enc = (const int*)d_in[2];
    const int*   len_dec = (const int*)d_in[3];
    const float* E       = (const float*)d_in[4];
    const float* enc_W   = (const float*)d_in[5];
    const float* enc_b   = (const float*)d_in[6];
    const float* dec_W   = (const float*)d_in[7];
    const float* dec_b   = (const float*)d_in[8];
    const float* proj_W  = (const float*)d_in[9];
    float* out = (float*)d_out;

    float *xz_e, *xz_d, *X, *state, *hs, *WtP, *WtE, *WtD;
    cudaGetSymbolAddress((void**)&xz_e,  g_xz_enc);
    cudaGetSymbolAddress((void**)&xz_d,  g_xz_dec);
    cudaGetSymbolAddress((void**)&X,     g_X);
    cudaGetSymbolAddress((void**)&state, g_state);
    cudaGetSymbolAddress((void**)&hs,    g_hs);
    cudaGetSymbolAddress((void**)&WtP,   g_WtP);
    cudaGetSymbolAddress((void**)&WtE,   g_WtE);
    cudaGetSymbolAddress((void**)&WtD,   g_WtD);
    float* c   = state;
    float* hp0 = state + BB * HH;
    float* hp1 = state + 2 * BB * HH;
    unsigned* bars = (unsigned*)(state + 3 * BB * HH);

    cudaFuncSetAttribute(tf32_gemm_kernel,
                         cudaFuncAttributeMaxDynamicSharedMemorySize, GEMM_SMEM);

    // [0] enc transpose, [1] enc embed (+zero bars), [2] enc input GEMM
    transpose_kernel<<<dim3(G4 / 32, DD / 32), dim3(32, 8)>>>(enc_W, WtE, DD, G4);
    embed_kernel<<<MROW, 128>>>(enc_ids, E, X, bars);
    tf32_gemm_kernel<<<dim3(G4 / 128, MROW / 128), 256, GEMM_SMEM>>>(X, WtE, enc_b, xz_e, G4);
    // [3] encoder LSTM  <- profiled (ncu launch index 3)
    lstm_persistent4<<<NBLK, 512>>>(xz_e, enc_W + (size_t)DD * G4, len_enc,
                                    c, hp0, hp1, nullptr, bars, 0);

    // [4..6] decoder preprocessing
    transpose_kernel<<<dim3(G4 / 32, DD / 32), dim3(32, 8)>>>(dec_W, WtD, DD, G4);
    embed_kernel<<<MROW, 128>>>(dec_ids, E, X, nullptr);
    tf32_gemm_kernel<<<dim3(G4 / 128, MROW / 128), 256, GEMM_SMEM>>>(X, WtD, dec_b, xz_d, G4);
    // [7] decoder LSTM
    lstm_persistent4<<<NBLK, 512>>>(xz_d, dec_W + (size_t)DD * G4, len_dec,
                                    c, hp0, hp1, hs, bars + 4, 1);

    // [8] proj transpose, [9] vocab projection
    transpose_kernel<<<dim3(VV / 32, DD / 32), dim3(32, 8)>>>(proj_W, WtP, DD, VV);
    tf32_gemm_kernel<<<dim3(VV / 128, MROW / 128), 256, GEMM_SMEM>>>(hs, WtP, nullptr, out, VV);
}

// round 10
// speedup vs baseline: 1.4721x; 1.3479x over previous
#include <cuda_runtime.h>
#include <math.h>
#include <stdint.h>

// Problem constants
#define BB   32
#define TT   64
#define DD   512
#define HH   512
#define VV   32000
#define G4   2048
#define MROW 2048    // T*B

#define NBLK 128

// ---------------- scratch (__device__ globals) -------------------------------
__device__ float g_xz_enc[MROW * G4];
__device__ float g_xz_dec[MROW * G4];
__device__ float g_X[MROW * DD];
// state: c [32*512] | hp0 [16384] | hp1 [16384] | bars [256 uints]
// hp layout per bq (4096 floats): [k:512][pair:4][half:2]
__device__ float g_state[3 * BB * HH + 256];
__device__ float g_hs[BB * TT * HH];
__device__ float g_WtP[(size_t)VV * DD];
__device__ float g_WtE[(size_t)G4 * DD];
__device__ float g_WtD[(size_t)G4 * DD];

__device__ __forceinline__ float sigf(float x) { return 1.0f / (1.0f + expf(-x)); }

__device__ __forceinline__ float f2tf(float x) {
    uint32_t r;
    asm("cvt.rna.tf32.f32 %0, %1;" : "=r"(r) : "f"(x));
    return __uint_as_float(r);
}

__device__ __forceinline__ uint32_t s2u(const void* p) {
    uint32_t a;
    asm("{ .reg .u64 t; cvta.to.shared.u64 t, %1; cvt.u32.u64 %0, t; }" : "=r"(a) : "l"(p));
    return a;
}

#define CP_ASYNC16(sdst, gsrc) \
    asm volatile("cp.async.cg.shared.global [%0], [%1], 16;" :: "r"(sdst), "l"(gsrc))
#define CP_COMMIT() asm volatile("cp.async.commit_group;" ::: "memory")
#define CP_WAIT1()  asm volatile("cp.async.wait_group 1;" ::: "memory")
#define CP_WAIT0()  asm volatile("cp.async.wait_group 0;" ::: "memory")

#define LDSM_X4(r0, r1, r2, r3, addr) \
    asm volatile("ldmatrix.sync.aligned.m8n8.x4.shared.b16 {%0,%1,%2,%3}, [%4];" \
        : "=r"(r0), "=r"(r1), "=r"(r2), "=r"(r3) : "r"(addr))

#define MMA_TF32(c, a, b0, b1) \
    asm volatile("mma.sync.aligned.m16n8k8.row.col.f32.tf32.tf32.f32 " \
        "{%0,%1,%2,%3}, {%4,%5,%6,%7}, {%8,%9}, {%0,%1,%2,%3};" \
        : "+f"((c)[0]), "+f"((c)[1]), "+f"((c)[2]), "+f"((c)[3]) \
        : "r"((a)[0]), "r"((a)[1]), "r"((a)[2]), "r"((a)[3]), "r"(b0), "r"(b1))

// packed fp32x2 ops
__device__ __forceinline__ void ffma2(unsigned long long& d, unsigned long long a,
                                      unsigned long long b) {
    asm("fma.rn.f32x2 %0, %1, %2, %0;" : "+l"(d) : "l"(a), "l"(b));
}
__device__ __forceinline__ unsigned long long fadd2(unsigned long long a,
                                                    unsigned long long b) {
    unsigned long long d;
    asm("add.rn.f32x2 %0, %1, %2;" : "=l"(d) : "l"(a), "l"(b));
    return d;
}
__device__ __forceinline__ unsigned long long packf2(float x, float y) {
    unsigned long long r;
    asm("mov.b64 %0, {%1, %2};" : "=l"(r) : "r"(__float_as_uint(x)), "r"(__float_as_uint(y)));
    return r;
}
__device__ __forceinline__ void unpackf2(unsigned long long v, float& x, float& y) {
    uint32_t a, b;
    asm("mov.b64 {%0, %1}, %2;" : "=r"(a), "=r"(b) : "l"(v));
    x = __uint_as_float(a);
    y = __uint_as_float(b);
}

// ---------------- small kernels ---------------------------------------------
__global__ void transpose_kernel(const float* __restrict__ src, float* __restrict__ dst,
                                 int R, int C) {
    __shared__ float tile[32][33];
    int c0 = blockIdx.x * 32, r0 = blockIdx.y * 32;
    int tx = threadIdx.x, ty = threadIdx.y;  // (32, 8)
    #pragma unroll
    for (int i = 0; i < 32; i += 8)
        tile[ty + i][tx] = src[(size_t)(r0 + ty + i) * C + c0 + tx];
    __syncthreads();
    #pragma unroll
    for (int i = 0; i < 32; i += 8)
        dst[(size_t)(c0 + ty + i) * R + r0 + tx] = f2tf(tile[tx][ty + i]);
}

// embed + zero the (padded) LSTM grid-barrier counters
__global__ void embed_kernel(const int* __restrict__ ids, const float* __restrict__ E,
                             float* __restrict__ X, unsigned* __restrict__ bars) {
    if (bars && blockIdx.x < 2)
        bars[blockIdx.x * 128 + threadIdx.x] = 0u;
    int r = blockIdx.x;
    int t = r >> 5;
    int b = r & 31;
    int tok = ids[b * TT + t];
    const float4* src = (const float4*)(E + (size_t)tok * DD);
    float4 v = src[threadIdx.x];
    v.x = f2tf(v.x); v.y = f2tf(v.y); v.z = f2tf(v.z); v.w = f2tf(v.w);
    ((float4*)(X + (size_t)r * DD))[threadIdx.x] = v;
}

// ---------------- tf32 mma.sync GEMM (BN=128, validated R6) ------------------
__device__ __forceinline__ void ld_tile(const float* __restrict__ src, size_t row0,
                                        int kc, uint32_t sbase, int tid) {
    #pragma unroll
    for (int i = 0; i < 4; i++) {
        int s = tid + i * 256;
        int r = s >> 3, cs = s & 7;
        const float* g = src + (row0 + r) * DD + kc * 32 + cs * 4;
        uint32_t off = (uint32_t)(r * 128 + cs * 16) ^ ((r & 7) << 4);
        CP_ASYNC16(sbase + off, g);
    }
}

#define TILE_B 16384
#define GEMM_SMEM (1024 + 4 * TILE_B)

__global__ __launch_bounds__(256)
void tf32_gemm_kernel(const float* __restrict__ A, const float* __restrict__ Bt,
                      const float* __restrict__ bias, float* __restrict__ C, int ldc) {
    extern __shared__ char smem_raw[];
    uint32_t raw_u = s2u(smem_raw);
    uint32_t base_u = (raw_u + 1023) & ~1023u;
    uint32_t sa_u[2] = { base_u,          base_u + 2 * TILE_B };
    uint32_t sb_u[2] = { base_u + TILE_B, base_u + 3 * TILE_B };

    int tid = threadIdx.x;
    int lane = tid & 31, wid = tid >> 5;
    int wm = wid & 3, wn = wid >> 2;
    size_t m0 = (size_t)blockIdx.y * 128;
    size_t n0 = (size_t)blockIdx.x * 128;

    int q = lane >> 3;
    int ar = wm * 32 + (q & 1) * 8 + (lane & 7);
    uint32_t apre[2], amask = (uint32_t)((ar & 7) << 4);
    apre[0] = (uint32_t)(ar * 128 + (q >> 1) * 16);
    apre[1] = apre[0] + 16 * 128;
    int br = wn * 64 + (q >> 1) * 8 + (lane & 7);
    uint32_t bpre[4], bmask = (uint32_t)((br & 7) << 4);
    bpre[0] = (uint32_t)(br * 128 + (q & 1) * 16);
    bpre[1] = bpre[0] + 16 * 128;
    bpre[2] = bpre[0] + 32 * 128;
    bpre[3] = bpre[0] + 48 * 128;

    float acc[2][8][4];
    #pragma unroll
    for (int i = 0; i < 2; i++)
        #pragma unroll
        for (int j = 0; j < 8; j++)
            #pragma unroll
            for (int k = 0; k < 4; k++) acc[i][j][k] = 0.0f;

    ld_tile(A,  m0, 0, sa_u[0], tid);
    ld_tile(Bt, n0, 0, sb_u[0], tid);
    CP_COMMIT();

    int buf = 0;
    #pragma unroll 1
    for (int it = 0; it < DD / 32; it++) {
        if (it + 1 < DD / 32) {
            ld_tile(A,  m0, it + 1, sa_u[buf ^ 1], tid);
            ld_tile(Bt, n0, it + 1, sb_u[buf ^ 1], tid);
            CP_COMMIT();
            CP_WAIT1();
        } else {
            CP_WAIT0();
        }
        __syncthreads();

        uint32_t As = sa_u[buf], Bs = sb_u[buf];
        #pragma unroll
        for (int ks = 0; ks < 4; ks++) {
            uint32_t a[2][4], b[4][4];
            #pragma unroll
            for (int mt = 0; mt < 2; mt++)
                LDSM_X4(a[mt][0], a[mt][1], a[mt][2], a[mt][3],
                        As + (((apre[mt] + ks * 32) ^ amask)));
            #pragma unroll
            for (int np = 0; np < 4; np++)
                LDSM_X4(b[np][0], b[np][1], b[np][2], b[np][3],
                        Bs + (((bpre[np] + ks * 32) ^ bmask)));
            #pragma unroll
            for (int mt = 0; mt < 2; mt++)
                #pragma unroll
                for (int nt = 0; nt < 8; nt++)
                    MMA_TF32(acc[mt][nt], a[mt], b[nt >> 1][(nt & 1) * 2],
                             b[nt >> 1][(nt & 1) * 2 + 1]);
        }
        __syncthreads();
        buf ^= 1;
    }

    int g = lane >> 2, tg = lane & 3;
    #pragma unroll
    for (int mt = 0; mt < 2; mt++) {
        size_t row = m0 + wm * 32 + mt * 16 + g;
        #pragma unroll
        for (int nt = 0; nt < 8; nt++) {
            size_t col = n0 + wn * 64 + nt * 8 + 2 * tg;
            float b0 = 0.f, b1 = 0.f;
            if (bias) { b0 = bias[col]; b1 = bias[col + 1]; }
            float2 v0 = make_float2(acc[mt][nt][0] + b0, acc[mt][nt][1] + b1);
            float2 v1 = make_float2(acc[mt][nt][2] + b0, acc[mt][nt][3] + b1);
            *(float2*)(C + row * (size_t)ldc + col)       = v0;
            *(float2*)(C + (row + 8) * (size_t)ldc + col) = v1;
        }
    }
}

// ---------------- persistent LSTM v5 (= v2 + 3 surgical fixes) ---------------
// 128 blocks = 32 col-tiles x 4 batch-quarters, 256 threads (v2 layout).
// Thread (jl, kq): jl = w*8 + (l>>2) column 0..63, kq = l&3 k-quarter (128 k).
// Fix 1: h layout [k][pair] -> 2x LDS.128 per k instead of 4x LDS.64.
// Fix 2: barrier counters padded 128 B apart.
// Fix 3: xz[t+1] prefetched before the barrier wait.
__global__ __launch_bounds__(256)
void lstm_persistent5(const float* __restrict__ xz, const float* __restrict__ Wh,
                      const int* __restrict__ len, float* __restrict__ c_glob,
                      float* __restrict__ hp0f, float* __restrict__ hp1f,
                      float* __restrict__ hs, unsigned* __restrict__ bar, int dec) {
    __shared__ unsigned long long hp_s[512 * 4];   // [k][pair]
    __shared__ float z_s[64][12];
    int tid = threadIdx.x;
    int w = tid >> 5, l = tid & 31;
    int jl = w * 8 + (l >> 2);          // 0..63
    int kq = l & 3;                     // 0..3, owns k = 4i+kq
    int ux = blockIdx.x & 31, bq = blockIdx.x >> 5;
    int u0 = ux * 16, b0 = bq * 8;
    int jg = ((jl >> 4) << 9) + u0 + (jl & 15);
    unsigned* mybar = bar + bq * 32;     // 128-byte padded counter

    // weights: thread owns k = 4i + kq, column jg (128 regs, as v2)
    float wreg[128];
    #pragma unroll
    for (int i = 0; i < 128; i++)
        wreg[i] = Wh[(size_t)(4 * i + kq) * G4 + jg];

    // gate-thread identity (tid < 128)
    int u = tid & 15, bb = (tid >> 4) & 7;
    int b = b0 + bb, uu = u0 + u;
    int myl = 0;
    float cval = 0.0f;
    if (tid < 128) {
        myl = len[b];
        if (dec) cval = c_glob[(size_t)b * HH + uu];
    }

    const float4* hpg[2] = {
        (const float4*)(hp0f + (size_t)bq * 4096),
        (const float4*)(hp1f + (size_t)bq * 4096) };
    float* hpw[2] = { hp0f + (size_t)bq * 4096, hp1f + (size_t)bq * 4096 };
    unsigned target = 0;

    // prefetch xz for step 0
    float xzv[4];
    if (tid < 128) {
        const float* xp = xz + (size_t)(0 * BB + b) * G4 + uu;
        #pragma unroll
        for (int g = 0; g < 4; g++) xzv[g] = xp[g * HH];
    }

    #pragma unroll 1
    for (int t = 0; t < TT; t++) {
        bool first = (t == 0) && (dec == 0);   // encoder h0 == 0
        if (!first) {
            {   // stage 16 KB of packed h: 1024 float4, 4 per thread
                const float4* src = hpg[t & 1];
                float4* dst = (float4*)hp_s;
                #pragma unroll
                for (int i = 0; i < 4; i++) dst[tid + i * 256] = src[tid + i * 256];
            }
            __syncthreads();

            unsigned long long acc2[4] = {0ull, 0ull, 0ull, 0ull};
            const longlong2* hp2 = (const longlong2*)hp_s;
            #pragma unroll
            for (int i = 0; i < 128; i++) {
                int k = 4 * i + kq;
                unsigned long long wd = packf2(wreg[i], wreg[i]);
                longlong2 h01 = hp2[k * 2];
                longlong2 h23 = hp2[k * 2 + 1];
                ffma2(acc2[0], wd, (unsigned long long)h01.x);
                ffma2(acc2[1], wd, (unsigned long long)h01.y);
                ffma2(acc2[2], wd, (unsigned long long)h23.x);
                ffma2(acc2[3], wd, (unsigned long long)h23.y);
            }
            // reduce across 4 kq lanes (2 rounds), then lane kq owns pair kq
            #pragma unroll
            for (int r = 1; r < 4; r <<= 1)
                #pragma unroll
                for (int p = 0; p < 4; p++)
                    acc2[p] = fadd2(acc2[p],
                        __shfl_xor_sync(0xffffffffu, acc2[p], r, 4));
            {
                float x, y;
                unpackf2(acc2[kq], x, y);
                z_s[jl][2 * kq]     = x;
                z_s[jl][2 * kq + 1] = y;
            }
            __syncthreads();
        }

        if (tid < 128) {
            float zi = xzv[0], zj = xzv[1], zf = xzv[2], zo = xzv[3];
            if (!first) {
                zi += z_s[u][bb];
                zj += z_s[16 + u][bb];
                zf += z_s[32 + u][bb];
                zo += z_s[48 + u][bb];
            }
            // write h_next in [k][pair][half] layout
            float* hn_dst = hpw[(t + 1) & 1] + uu * 8 + (bb >> 1) * 2 + (bb & 1);
            if (t < myl) {
                cval = cval * sigf(zf + 1.0f) + sigf(zi) * tanhf(zj);
                float hn = tanhf(cval) * sigf(zo);
                *hn_dst = hn;
                if (dec) hs[((size_t)b * TT + t) * HH + uu] = f2tf(hn);
            } else {
                float hprev = first ? 0.0f
                    : ((const float*)hp_s)[uu * 8 + (bb >> 1) * 2 + (bb & 1)];
                *hn_dst = hprev;
                if (dec) hs[((size_t)b * TT + t) * HH + uu] = 0.0f;
            }
            // prefetch xz for t+1 BEFORE the barrier (independent of h)
            if (t + 1 < TT) {
                const float* xp = xz + (size_t)((t + 1) * BB + b) * G4 + uu;
                #pragma unroll
                for (int g = 0; g < 4; g++) xzv[g] = xp[g * HH];
            }
        }
        __syncthreads();
        // per-bq grid barrier (32 blocks), padded counter
        target += 32;
        if (tid == 0) {
            asm volatile("red.release.gpu.global.add.u32 [%0], %1;"
                         :: "l"(mybar), "r"(1u) : "memory");
            unsigned v;
            do {
                asm volatile("ld.acquire.gpu.u32 %0, [%1];" : "=r"(v) : "l"(mybar));
            } while (v < target);
        }
        __syncthreads();
    }
    if (tid < 128) c_glob[(size_t)b * HH + uu] = cval;
}

// ---------------- host launch ------------------------------------------------
extern "C" void kernel_launch(void* const* d_in, const int* in_sizes, int n_in,
                              void* d_out, int out_size) {
    const int*   enc_ids = (const int*)d_in[0];
    const int*   dec_ids = (const int*)d_in[1];
    const int*   len_enc = (const int*)d_in[2];
    const int*   len_dec = (const int*)d_in[3];
    const float* E       = (const float*)d_in[4];
    const float* enc_W   = (const float*)d_in[5];
    const float* enc_b   = (const float*)d_in[6];
    const float* dec_W   = (const float*)d_in[7];
    const float* dec_b   = (const float*)d_in[8];
    const float* proj_W  = (const float*)d_in[9];
    float* out = (float*)d_out;

    float *xz_e, *xz_d, *X, *state, *hs, *WtP, *WtE, *WtD;
    cudaGetSymbolAddress((void**)&xz_e,  g_xz_enc);
    cudaGetSymbolAddress((void**)&xz_d,  g_xz_dec);
    cudaGetSymbolAddress((void**)&X,     g_X);
    cudaGetSymbolAddress((void**)&state, g_state);
    cudaGetSymbolAddress((void**)&hs,    g_hs);
    cudaGetSymbolAddress((void**)&WtP,   g_WtP);
    cudaGetSymbolAddress((void**)&WtE,   g_WtE);
    cudaGetSymbolAddress((void**)&WtD,   g_WtD);
    float* c   = state;
    float* hp0 = state + BB * HH;
    float* hp1 = state + 2 * BB * HH;
    unsigned* bars = (unsigned*)(state + 3 * BB * HH);  // 256 padded uints

    cudaFuncSetAttribute(tf32_gemm_kernel,
                         cudaFuncAttributeMaxDynamicSharedMemorySize, GEMM_SMEM);

    // [0] enc transpose, [1] enc embed (+zero padded bars), [2] enc input GEMM
    transpose_kernel<<<dim3(G4 / 32, DD / 32), dim3(32, 8)>>>(enc_W, WtE, DD, G4);
    embed_kernel<<<MROW, 128>>>(enc_ids, E, X, bars);
    tf32_gemm_kernel<<<dim3(G4 / 128, MROW / 128), 256, GEMM_SMEM>>>(X, WtE, enc_b, xz_e, G4);
    // [3] encoder LSTM  <- profiled (ncu launch index 3)
    lstm_persistent5<<<NBLK, 256>>>(xz_e, enc_W + (size_t)DD * G4, len_enc,
                                    c, hp0, hp1, nullptr, bars, 0);

    // [4..6] decoder preprocessing
    transpose_kernel<<<dim3(G4 / 32, DD / 32), dim3(32, 8)>>>(dec_W, WtD, DD, G4);
    embed_kernel<<<MROW, 128>>>(dec_ids, E, X, nullptr);
    tf32_gemm_kernel<<<dim3(G4 / 128, MROW / 128), 256, GEMM_SMEM>>>(X, WtD, dec_b, xz_d, G4);
    // [7] decoder LSTM (padded counters at bars+128)
    lstm_persistent5<<<NBLK, 256>>>(xz_d, dec_W + (size_t)DD * G4, len_dec,
                                    c, hp0, hp1, hs, bars + 128, 1);

    // [8] proj transpose, [9] vocab projection
    transpose_kernel<<<dim3(VV / 32, DD / 32), dim3(32, 8)>>>(proj_W, WtP, DD, VV);
    tf32_gemm_kernel<<<dim3(VV / 128, MROW / 128), 256, GEMM_SMEM>>>(hs, WtP, nullptr, out, VV);
}